// round 8
// baseline (speedup 1.0000x reference)
#include <cuda_runtime.h>
#include <math.h>

// ---------------- problem constants ----------------
#define B    8
#define C    128
#define Fk   8        // f dim (index 0 is c0, 1..7 are c_rest)
#define K    7
#define H64  64
#define HW   4096
#define HP   256
#define HWQ  4        // hw quarters: 1024 px each, 256 threads x float4
#define NCC  32       // channel groups
#define CPG  4        // channels per group
#define NCHUNK (B * HWQ * NCC)   // 1024 blocks for the two big passes
#define TPB  256

#define OUT1_ELEMS ((size_t)B * 257 * HW)
#define OUT2_ELEMS ((size_t)B * HW)

// ---------------- scratch ----------------
__device__ float g_t[B * HW];
__device__ float g_m[B * K * HW];
__device__ float g_cm[B * K * HW];           // softmax weights (917 KB, L2-hot)
__device__ float g_partG[NCHUNK * K];
__device__ float g_partS[B * HWQ * K];

// ============================================================
// Kernel 1: resize masks 256->64 (linear, antialias=False) + threshold.
// out[i,j] = avg of in[{4i+1,4i+2} x {4j+1,4j+2}] > 0.5
// ============================================================
__device__ __forceinline__ float mask_at4(const float* __restrict__ p, int r0, int j) {
    float4 a = *(const float4*)(p + (size_t)r0 * HP + 4 * j);
    float4 b = *(const float4*)(p + (size_t)(r0 + 1) * HP + 4 * j);
    float y = 0.25f * (a.y + a.z + b.y + b.z);
    return (y > 0.5f) ? 1.0f : 0.0f;
}

__global__ __launch_bounds__(TPB)
void k_masks(const float* __restrict__ vt, const float* __restrict__ va) {
    int idx = blockIdx.x * TPB + threadIdx.x;   // 0 .. B*HW-1
    int b  = idx >> 12;
    int hw = idx & (HW - 1);
    int i  = hw >> 6;
    int j  = hw & 63;
    int r0 = 4 * i + 1;

    g_t[idx] = mask_at4(vt + (size_t)b * HP * HP, r0, j);
    #pragma unroll
    for (int k = 0; k < K; k++)
        g_m[((size_t)b * K + k) * HW + hw] =
            mask_at4(va + ((size_t)b * K + k) * HP * HP, r0, j);
}

// ============================================================
// Kernel 2: partial reductions for S[b,k], G[b,k]; also emits the c0 copy
// (output channels [0,128)) since c0 is already in registers here.
// grid = 1024: (b, hwq, cg). 256 threads x float4 = 1024 px, 4 channels.
// ============================================================
__global__ __launch_bounds__(TPB, 5)
void k_pass1(const float* __restrict__ feats, float* __restrict__ out) {
    __shared__ float red[8][2 * K];
    const int tid  = threadIdx.x;
    const int lane = tid & 31;
    const int wrp  = tid >> 5;

    int chunk = blockIdx.x;
    int cg  = chunk & (NCC - 1);
    int hwq = (chunk >> 5) & (HWQ - 1);
    int b   = chunk >> 7;
    int hw0 = hwq * 1024 + tid * 4;

    const float* base = feats + ((size_t)(b * C + cg * CPG)) * Fk * HW + hw0;
    float* ob = out + (size_t)b * 257 * HW + hw0;

    float4 acc[K];
    #pragma unroll
    for (int k = 0; k < K; k++) acc[k] = make_float4(0.f, 0.f, 0.f, 0.f);

    #pragma unroll
    for (int c = 0; c < CPG; c++) {
        const float* p = base + (size_t)c * Fk * HW;
        float4 c0 = *(const float4*)p;
        *(float4*)(ob + (size_t)(cg * CPG + c) * HW) = c0;   // channels [0,128)
        #pragma unroll
        for (int k = 0; k < K; k++) {
            float4 r = *(const float4*)(p + (size_t)(k + 1) * HW);
            acc[k].x = fmaf(c0.x, r.x, acc[k].x);
            acc[k].y = fmaf(c0.y, r.y, acc[k].y);
            acc[k].z = fmaf(c0.z, r.z, acc[k].z);
            acc[k].w = fmaf(c0.w, r.w, acc[k].w);
        }
    }

    const float4 t4 = *(const float4*)(g_t + b * HW + hw0);
    float vals[2 * K];
    #pragma unroll
    for (int k = 0; k < K; k++) {
        float4 m4 = *(const float4*)(g_m + ((size_t)(b * K + k)) * HW + hw0);
        float4 w;
        w.x = t4.x * m4.x; w.y = t4.y * m4.y;
        w.z = t4.z * m4.z; w.w = t4.w * m4.w;
        vals[k]     = w.x * acc[k].x + w.y * acc[k].y + w.z * acc[k].z + w.w * acc[k].w;
        vals[K + k] = w.x + w.y + w.z + w.w;
    }

    #pragma unroll
    for (int v = 0; v < 2 * K; v++) {
        float x = vals[v];
        #pragma unroll
        for (int o = 16; o > 0; o >>= 1) x += __shfl_down_sync(0xFFFFFFFFu, x, o);
        if (lane == 0) red[wrp][v] = x;
    }
    __syncthreads();
    if (tid < 2 * K) {
        float x = 0.f;
        #pragma unroll
        for (int w = 0; w < 8; w++) x += red[w][tid];
        if (tid < K)
            g_partG[chunk * K + tid] = x;
        else if (cg == 0)
            g_partS[(b * HWQ + hwq) * K + (tid - K)] = x;
    }
}

// ============================================================
// Kernel 3: per-pixel softmax weights cm[k] -> g_cm, plus c_mask outputs.
// ============================================================
__global__ __launch_bounds__(TPB)
void k_cm(float* __restrict__ out, int write_second) {
    __shared__ float sgs[K];
    const int tid = threadIdx.x;
    int idx = blockIdx.x * TPB + tid;
    int b   = idx >> 12;
    int hw  = idx & (HW - 1);

    if (tid < K) {
        float G = 0.f;
        #pragma unroll 8
        for (int j = 0; j < HWQ * NCC; j++)
            G += g_partG[(size_t)(b * HWQ * NCC + j) * K + tid];
        float S = 0.f;
        #pragma unroll
        for (int j = 0; j < HWQ; j++)
            S += g_partS[(size_t)(b * HWQ + j) * K + tid];
        sgs[tid] = (S < 1e-4f) ? 0.f : G / (S * (float)C);
    }
    __syncthreads();

    const float* mb = g_m + (size_t)b * K * HW + hw;
    float m[K];
    #pragma unroll
    for (int k = 0; k < K; k++) m[k] = mb[(size_t)k * HW];

    float mx = sgs[0] * m[0];
    #pragma unroll
    for (int k = 1; k < K; k++) mx = fmaxf(mx, sgs[k] * m[k]);

    float e[K], s = 0.f;
    #pragma unroll
    for (int k = 0; k < K; k++) {
        e[k] = __expf(sgs[k] * m[k] - mx) * m[k];
        s += e[k];
    }
    float inv = 1.f / (s + ((s < 1e-4f) ? 1.f : 0.f));

    float* cmb = g_cm + (size_t)b * K * HW + hw;
    #pragma unroll
    for (int k = 0; k < K; k++) cmb[(size_t)k * HW] = e[k] * inv;

    float cmask = 1.f - s * inv;     // 1 - sum_k cm*m
    out[(size_t)b * 257 * HW + (size_t)256 * HW + hw] = cmask;
    if (write_second)
        out[OUT1_ELEMS + (size_t)b * HW + hw] = cmask;
}

// ============================================================
// Kernel 4 (minimal): c_out only. 7 loads + 1 store per channel.
// ============================================================
__global__ __launch_bounds__(TPB, 6)
void k_pass2(const float* __restrict__ feats, float* __restrict__ out) {
    __shared__ float4 cmbuf[K * TPB];      // 28 KB
    const int tid = threadIdx.x;

    int bid = (gridDim.x - 1) - blockIdx.x;   // reversed vs pass1
    int cg  = bid & (NCC - 1);
    int hwq = (bid >> 5) & (HWQ - 1);
    int b   = bid >> 7;
    int hw0 = hwq * 1024 + tid * 4;

    const float* cmg = g_cm + (size_t)b * K * HW + hw0;   // L2-hot
    #pragma unroll
    for (int k = 0; k < K; k++)
        cmbuf[k * TPB + tid] = *(const float4*)(cmg + (size_t)k * HW);
    __syncthreads();

    const float* base = feats + ((size_t)(b * C + cg * CPG)) * Fk * HW + hw0 + HW; // +HW: skip c0
    float* ob = out + (size_t)(b * 257 + 128 + cg * CPG) * HW + hw0;

    #pragma unroll
    for (int c = 0; c < CPG; c++) {
        const float* p = base + (size_t)c * Fk * HW;
        float4 a = make_float4(0.f, 0.f, 0.f, 0.f);
        #pragma unroll
        for (int k = 0; k < K; k++) {
            float4 cm = cmbuf[k * TPB + tid];
            float4 r  = *(const float4*)(p + (size_t)k * HW);
            a.x = fmaf(cm.x, r.x, a.x);
            a.y = fmaf(cm.y, r.y, a.y);
            a.z = fmaf(cm.z, r.z, a.z);
            a.w = fmaf(cm.w, r.w, a.w);
        }
        *(float4*)(ob + (size_t)c * HW) = a;   // channels [128,256)
    }
}

// ============================================================
extern "C" void kernel_launch(void* const* d_in, const int* in_sizes, int n_in,
                              void* d_out, int out_size) {
    const float* feats = (const float*)d_in[0];   // (8,128,8,64,64)
    const float* vt    = (const float*)d_in[1];   // (8,1,256,256)
    const float* va    = (const float*)d_in[2];   // (8,1,7,256,256)
    float* out = (float*)d_out;

    int write_second = ((size_t)out_size >= OUT1_ELEMS + OUT2_ELEMS) ? 1 : 0;

    k_masks<<<(B * HW) / TPB, TPB>>>(vt, va);
    k_pass1<<<NCHUNK, TPB>>>(feats, out);
    k_cm<<<(B * HW) / TPB, TPB>>>(out, write_second);
    k_pass2<<<NCHUNK, TPB>>>(feats, out);
}